// round 2
// baseline (speedup 1.0000x reference)
#include <cuda_runtime.h>
#include <math.h>

#define CIN 2048
#define NB  64
#define NK  32
#define DI  8
#define DO  16
#define EPSQ 1e-7f

// Scratch (allocation-free: __device__ globals)
__device__ float g_xT[CIN * DI * NB];    // xT[c][j][b]  (4 MB)
__device__ float g_s [NB * NK * DO];     // s accumulator (reused for s1 and s2)
__device__ float g_v1[NB * NK * DO];     // v after iteration 1
__device__ float g_a [NK * CIN * NB];    // aT[k][c][b]; softmaxed in place to cc (16 MB)

__global__ void k_zero_s() {
    int t = blockIdx.x * blockDim.x + threadIdx.x;
    if (t < NB * NK * DO) g_s[t] = 0.f;
}

// xT[(c*8 + j)*64 + b] = x[b][c][j]
__global__ void k_transpose(const float* __restrict__ x) {
    int idx = blockIdx.x * blockDim.x + threadIdx.x;
    if (idx < CIN * DI * NB) {
        int b = idx & 63;
        int j = (idx >> 6) & 7;
        int c = idx >> 9;
        g_xT[idx] = __ldg(&x[(b * CIN + c) * DI + j]);
    }
}

// Pass A: s1[b,k,i] += sum_{c,j} W[k,c,i,j] * x[b,c,j]
// grid (32 c-slices, 32 k), block 64 threads (lane = b). W broadcast via LDG.
__global__ void k_passA(const float* __restrict__ W) {
    int k  = blockIdx.y;
    int b  = threadIdx.x;
    int c0 = blockIdx.x * 64;
    float acc[DO];
#pragma unroll
    for (int i = 0; i < DO; i++) acc[i] = 0.f;

    for (int ci = 0; ci < 64; ci++) {
        int c = c0 + ci;
        const float* xp = &g_xT[c * (DI * NB) + b];
        float x0 = xp[0],   x1 = xp[64],  x2 = xp[128], x3 = xp[192];
        float x4 = xp[256], x5 = xp[320], x6 = xp[384], x7 = xp[448];
        const float4* wp = (const float4*)(W + ((size_t)k * CIN + c) * (DO * DI));
#pragma unroll
        for (int i = 0; i < DO; i++) {
            float4 wa = __ldg(&wp[2 * i]);
            float4 wb = __ldg(&wp[2 * i + 1]);
            acc[i] += wa.x * x0 + wa.y * x1 + wa.z * x2 + wa.w * x3
                    + wb.x * x4 + wb.y * x5 + wb.z * x6 + wb.w * x7;
        }
    }
#pragma unroll
    for (int i = 0; i < DO; i++)
        atomicAdd(&g_s[(b * NK + k) * DO + i], acc[i]);
}

// v1 = squash(s1 / 32)   (iteration-1 coupling coefficients are uniform 1/32)
__global__ void k_squash1() {
    int t = blockIdx.x * blockDim.x + threadIdx.x;
    if (t >= NB * NK) return;
    float s[DO];
    float sq = 0.f;
#pragma unroll
    for (int i = 0; i < DO; i++) {
        s[i] = g_s[t * DO + i] * (1.f / 32.f);
        sq += s[i] * s[i];
    }
    float scale = (sq / (1.f + sq)) * rsqrtf(sq + EPSQ);
#pragma unroll
    for (int i = 0; i < DO; i++) g_v1[t * DO + i] = s[i] * scale;
}

// Pass C: aT[k][c][b] = sum_i ( sum_j W[k,c,i,j] x[b,c,j] ) * v1[b,k,i]
__global__ void k_passC(const float* __restrict__ W) {
    int k  = blockIdx.y;
    int b  = threadIdx.x;
    int c0 = blockIdx.x * 64;
    float v[DO];
#pragma unroll
    for (int i = 0; i < DO; i++) v[i] = g_v1[(b * NK + k) * DO + i];

    for (int ci = 0; ci < 64; ci++) {
        int c = c0 + ci;
        const float* xp = &g_xT[c * (DI * NB) + b];
        float x0 = xp[0],   x1 = xp[64],  x2 = xp[128], x3 = xp[192];
        float x4 = xp[256], x5 = xp[320], x6 = xp[384], x7 = xp[448];
        const float4* wp = (const float4*)(W + ((size_t)k * CIN + c) * (DO * DI));
        float a = 0.f;
#pragma unroll
        for (int i = 0; i < DO; i++) {
            float4 wa = __ldg(&wp[2 * i]);
            float4 wb = __ldg(&wp[2 * i + 1]);
            float u = wa.x * x0 + wa.y * x1 + wa.z * x2 + wa.w * x3
                    + wb.x * x4 + wb.y * x5 + wb.z * x6 + wb.w * x7;
            a += u * v[i];
        }
        g_a[((size_t)k * CIN + c) * NB + b] = a;
    }
}

// Softmax over k (axis=1) at each (c, b); in place on g_a.
__global__ void k_softmax() {
    int idx = blockIdx.x * blockDim.x + threadIdx.x;  // c*64 + b
    if (idx >= CIN * NB) return;
    float vals[NK];
    float mx = -1e30f;
#pragma unroll
    for (int k = 0; k < NK; k++) {
        vals[k] = g_a[(size_t)k * (CIN * NB) + idx];
        mx = fmaxf(mx, vals[k]);
    }
    float sum = 0.f;
#pragma unroll
    for (int k = 0; k < NK; k++) {
        vals[k] = __expf(vals[k] - mx);
        sum += vals[k];
    }
    float inv = 1.f / sum;
#pragma unroll
    for (int k = 0; k < NK; k++)
        g_a[(size_t)k * (CIN * NB) + idx] = vals[k] * inv;
}

// Pass E: s2[b,k,i] += sum_{c,j} W[k,c,i,j] * (cc[b,k,c] * x[b,c,j])
__global__ void k_passE(const float* __restrict__ W) {
    int k  = blockIdx.y;
    int b  = threadIdx.x;
    int c0 = blockIdx.x * 64;
    float acc[DO];
#pragma unroll
    for (int i = 0; i < DO; i++) acc[i] = 0.f;

    for (int ci = 0; ci < 64; ci++) {
        int c = c0 + ci;
        float cc = g_a[((size_t)k * CIN + c) * NB + b];
        const float* xp = &g_xT[c * (DI * NB) + b];
        float x0 = xp[0]   * cc, x1 = xp[64]  * cc, x2 = xp[128] * cc, x3 = xp[192] * cc;
        float x4 = xp[256] * cc, x5 = xp[320] * cc, x6 = xp[384] * cc, x7 = xp[448] * cc;
        const float4* wp = (const float4*)(W + ((size_t)k * CIN + c) * (DO * DI));
#pragma unroll
        for (int i = 0; i < DO; i++) {
            float4 wa = __ldg(&wp[2 * i]);
            float4 wb = __ldg(&wp[2 * i + 1]);
            acc[i] += wa.x * x0 + wa.y * x1 + wa.z * x2 + wa.w * x3
                    + wb.x * x4 + wb.y * x5 + wb.z * x6 + wb.w * x7;
        }
    }
#pragma unroll
    for (int i = 0; i < DO; i++)
        atomicAdd(&g_s[(b * NK + k) * DO + i], acc[i]);
}

// out = squash(s2)
__global__ void k_squashF(float* __restrict__ out) {
    int t = blockIdx.x * blockDim.x + threadIdx.x;
    if (t >= NB * NK) return;
    float s[DO];
    float sq = 0.f;
#pragma unroll
    for (int i = 0; i < DO; i++) {
        s[i] = g_s[t * DO + i];
        sq += s[i] * s[i];
    }
    float scale = (sq / (1.f + sq)) * rsqrtf(sq + EPSQ);
#pragma unroll
    for (int i = 0; i < DO; i++) out[t * DO + i] = s[i] * scale;
}

extern "C" void kernel_launch(void* const* d_in, const int* in_sizes, int n_in,
                              void* d_out, int out_size) {
    // x: [64,2048,8] = 1048576 floats; W: [32,2048,16,8] = 8388608 floats
    const float* x = (const float*)d_in[0];
    const float* W = (const float*)d_in[1];
    if (n_in >= 2 && in_sizes[0] == 8388608 && in_sizes[1] == 1048576) {
        // defensive: swap if metadata order differs
        const float* t = x; x = W; W = t;
    }
    float* out = (float*)d_out;

    dim3 passGrid(32, 32);   // (c-slice, k)
    dim3 passBlk(64);        // lane = b

    k_transpose<<<(CIN * DI * NB + 255) / 256, 256>>>(x);
    k_zero_s<<<(NB * NK * DO + 255) / 256, 256>>>();
    k_passA<<<passGrid, passBlk>>>(W);
    k_squash1<<<(NB * NK + 127) / 128, 128>>>();
    k_passC<<<passGrid, passBlk>>>(W);
    k_softmax<<<(CIN * NB + 255) / 256, 256>>>();
    k_zero_s<<<(NB * NK * DO + 255) / 256, 256>>>();
    k_passE<<<passGrid, passBlk>>>(W);
    k_squashF<<<(NB * NK + 127) / 128, 128>>>(out);
}

// round 4
// speedup vs baseline: 1.8513x; 1.8513x over previous
#include <cuda_runtime.h>
#include <math.h>

#define CIN 2048
#define NB  64
#define NK  32
#define DI  8
#define DO  16
#define EPSQ 1e-7f
#define NSLICE 32
#define CPB 64          // c-values per block
#define NCG 4           // c-groups per block (256 threads / 64 b)

typedef unsigned long long ull;

// ---- scratch (__device__ globals; allocation-free) ----
__device__ float g_xT2 [CIN * NB * DI];          // xT2[c][b][j]   (4 MB)
__device__ float g_Wp  [NK * CIN * DI * DO];     // Wp[k][c][j][i] (33.5 MB)
__device__ float g_s   [NB * NK * DO];           // reduced s
__device__ float g_v1  [NB * NK * DO];           // v after iter 1
__device__ float g_a   [(size_t)NK * CIN * NB];  // aT[k][c][b] -> cc (16 MB)
__device__ float g_part[128 * NK * NB * DO];     // per-(slice,cg) partials (16.8 MB)

// ---- f32x2 helpers ----
__device__ __forceinline__ void fma2(ull& d, ull a, ull b) {
    asm("fma.rn.f32x2 %0, %1, %2, %0;" : "+l"(d) : "l"(a), "l"(b));
}
__device__ __forceinline__ ull pack2(float lo, float hi) {
    ull r; asm("mov.b64 %0, {%1, %2};" : "=l"(r) : "f"(lo), "f"(hi)); return r;
}
__device__ __forceinline__ float2 unpack2(ull v) {
    float2 f; asm("mov.b64 {%0, %1}, %2;" : "=f"(f.x), "=f"(f.y) : "l"(v)); return f;
}

// xT2[(c*64 + b)*8 + j] = x[b][c][j]
__global__ void k_transpose(const float* __restrict__ x) {
    int idx = blockIdx.x * blockDim.x + threadIdx.x;
    if (idx < CIN * NB * DI) {
        int j = idx & 7;
        int b = (idx >> 3) & 63;
        int c = idx >> 9;
        g_xT2[idx] = __ldg(&x[(b * CIN + c) * DI + j]);
    }
}

// Wp[((k*CIN+c)*8 + j)*16 + i] = W[((k*CIN+c)*16 + i)*8 + j]
__global__ void k_packW(const float* __restrict__ W) {
    int idx = blockIdx.x * blockDim.x + threadIdx.x;   // (k,c,j)
    if (idx >= NK * CIN * DI) return;
    int j  = idx & 7;
    int kc = idx >> 3;
    const float* src = W + (size_t)kc * (DO * DI) + j;
    float v[DO];
#pragma unroll
    for (int i = 0; i < DO; i++) v[i] = __ldg(&src[i * DI]);
    float4* dst = (float4*)(g_Wp + (size_t)idx * DO);
#pragma unroll
    for (int q = 0; q < 4; q++)
        dst[q] = make_float4(v[4*q], v[4*q+1], v[4*q+2], v[4*q+3]);
}

// ---------- Pass A: partials of s1[b,k,i] = sum_{c,j} W * x ----------
__global__ void __launch_bounds__(256) k_passA() {
    __shared__ float sW[CPB * DI * DO];   // 32 KB
    int k = blockIdx.y, slice = blockIdx.x;
    int c0 = slice * CPB;
    {
        const float4* src = (const float4*)(g_Wp + ((size_t)k * CIN + c0) * (DI * DO));
        float4* dst = (float4*)sW;
#pragma unroll 8
        for (int t = threadIdx.x; t < CPB * DI * DO / 4; t += 256) dst[t] = src[t];
    }
    __syncthreads();
    int b = threadIdx.x & 63, cg = threadIdx.x >> 6;

    ull acc[8];
#pragma unroll
    for (int p = 0; p < 8; p++) acc[p] = 0ull;

    for (int ci = cg; ci < CPB; ci += NCG) {
        const float4* xp = (const float4*)&g_xT2[(((size_t)c0 + ci) * NB + b) * DI];
        float4 xa = xp[0], xb = xp[1];
        ull xx[8] = { pack2(xa.x, xa.x), pack2(xa.y, xa.y), pack2(xa.z, xa.z), pack2(xa.w, xa.w),
                      pack2(xb.x, xb.x), pack2(xb.y, xb.y), pack2(xb.z, xb.z), pack2(xb.w, xb.w) };
        const ull* ws = (const ull*)(sW + ci * (DI * DO));
#pragma unroll
        for (int j = 0; j < 8; j++)
#pragma unroll
            for (int p = 0; p < 8; p++)
                fma2(acc[p], ws[j * 8 + p], xx[j]);
    }
    // g_part[r][k][b][i],  r = slice*4+cg
    int r = slice * NCG + cg;
    float4* out = (float4*)(g_part + (((size_t)r * NK + k) * NB + b) * DO);
#pragma unroll
    for (int q = 0; q < 4; q++) {
        float2 lo = unpack2(acc[2*q]), hi = unpack2(acc[2*q + 1]);
        out[q] = make_float4(lo.x, lo.y, hi.x, hi.y);
    }
}

// reduce 128 partials -> g_s   (vectorized over i quads)
__global__ void k_reduce() {
    int t = blockIdx.x * blockDim.x + threadIdx.x;   // 8192: (k,b,iq)
    if (t >= NK * NB * 4) return;
    const float4* p = (const float4*)g_part;
    float4 s = make_float4(0.f, 0.f, 0.f, 0.f);
#pragma unroll 8
    for (int rr = 0; rr < 128; rr++) {
        float4 v = p[(size_t)rr * (NK * NB * 4) + t];
        s.x += v.x; s.y += v.y; s.z += v.z; s.w += v.w;
    }
    int iq = t & 3, b = (t >> 2) & 63, k = t >> 8;
    ((float4*)(g_s + (b * NK + k) * DO))[iq] = s;
}

// v1 = squash(s / 32)
__global__ void k_squash1() {
    int t = blockIdx.x * blockDim.x + threadIdx.x;
    if (t >= NB * NK) return;
    float s[DO]; float sq = 0.f;
#pragma unroll
    for (int i = 0; i < DO; i++) { s[i] = g_s[t * DO + i] * (1.f / 32.f); sq += s[i] * s[i]; }
    float scale = (sq / (1.f + sq)) * rsqrtf(sq + EPSQ);
#pragma unroll
    for (int i = 0; i < DO; i++) g_v1[t * DO + i] = s[i] * scale;
}

// ---------- Pass C: aT[k][c][b] = sum_i u[b,k,c,i] * v1[b,k,i] ----------
__global__ void __launch_bounds__(256) k_passC() {
    __shared__ float sW[CPB * DI * DO];
    int k = blockIdx.y, slice = blockIdx.x;
    int c0 = slice * CPB;
    {
        const float4* src = (const float4*)(g_Wp + ((size_t)k * CIN + c0) * (DI * DO));
        float4* dst = (float4*)sW;
#pragma unroll 8
        for (int t = threadIdx.x; t < CPB * DI * DO / 4; t += 256) dst[t] = src[t];
    }
    __syncthreads();
    int b = threadIdx.x & 63, cg = threadIdx.x >> 6;

    ull v2[8];
    {
        const ull* vp = (const ull*)&g_v1[(b * NK + k) * DO];
#pragma unroll
        for (int p = 0; p < 8; p++) v2[p] = vp[p];
    }

    for (int ci = cg; ci < CPB; ci += NCG) {
        const float4* xp = (const float4*)&g_xT2[(((size_t)c0 + ci) * NB + b) * DI];
        float4 xa = xp[0], xb = xp[1];
        ull xx[8] = { pack2(xa.x, xa.x), pack2(xa.y, xa.y), pack2(xa.z, xa.z), pack2(xa.w, xa.w),
                      pack2(xb.x, xb.x), pack2(xb.y, xb.y), pack2(xb.z, xb.z), pack2(xb.w, xb.w) };
        const ull* ws = (const ull*)(sW + ci * (DI * DO));
        ull u2[8];
#pragma unroll
        for (int p = 0; p < 8; p++) u2[p] = 0ull;
#pragma unroll
        for (int j = 0; j < 8; j++)
#pragma unroll
            for (int p = 0; p < 8; p++)
                fma2(u2[p], ws[j * 8 + p], xx[j]);
        ull a2 = 0ull;
#pragma unroll
        for (int p = 0; p < 8; p++) fma2(a2, u2[p], v2[p]);
        float2 af = unpack2(a2);
        g_a[((size_t)k * CIN + (c0 + ci)) * NB + b] = af.x + af.y;
    }
}

// softmax over k at each (c,b), in place
__global__ void k_softmax() {
    int idx = blockIdx.x * blockDim.x + threadIdx.x;   // c*64+b
    if (idx >= CIN * NB) return;
    float vals[NK]; float mx = -1e30f;
#pragma unroll
    for (int k = 0; k < NK; k++) {
        vals[k] = g_a[(size_t)k * (CIN * NB) + idx];
        mx = fmaxf(mx, vals[k]);
    }
    float sum = 0.f;
#pragma unroll
    for (int k = 0; k < NK; k++) { vals[k] = __expf(vals[k] - mx); sum += vals[k]; }
    float inv = 1.f / sum;
#pragma unroll
    for (int k = 0; k < NK; k++) g_a[(size_t)k * (CIN * NB) + idx] = vals[k] * inv;
}

// ---------- Pass E: partials of s2[b,k,i] = sum_{c,j} W * (cc * x) ----------
__global__ void __launch_bounds__(256) k_passE() {
    __shared__ float sW[CPB * DI * DO];
    int k = blockIdx.y, slice = blockIdx.x;
    int c0 = slice * CPB;
    {
        const float4* src = (const float4*)(g_Wp + ((size_t)k * CIN + c0) * (DI * DO));
        float4* dst = (float4*)sW;
#pragma unroll 8
        for (int t = threadIdx.x; t < CPB * DI * DO / 4; t += 256) dst[t] = src[t];
    }
    __syncthreads();
    int b = threadIdx.x & 63, cg = threadIdx.x >> 6;

    ull acc[8];
#pragma unroll
    for (int p = 0; p < 8; p++) acc[p] = 0ull;

    for (int ci = cg; ci < CPB; ci += NCG) {
        float cc = g_a[((size_t)k * CIN + (c0 + ci)) * NB + b];
        const float4* xp = (const float4*)&g_xT2[(((size_t)c0 + ci) * NB + b) * DI];
        float4 xa = xp[0], xb = xp[1];
        ull xx[8] = { pack2(xa.x*cc, xa.x*cc), pack2(xa.y*cc, xa.y*cc),
                      pack2(xa.z*cc, xa.z*cc), pack2(xa.w*cc, xa.w*cc),
                      pack2(xb.x*cc, xb.x*cc), pack2(xb.y*cc, xb.y*cc),
                      pack2(xb.z*cc, xb.z*cc), pack2(xb.w*cc, xb.w*cc) };
        const ull* ws = (const ull*)(sW + ci * (DI * DO));
#pragma unroll
        for (int j = 0; j < 8; j++)
#pragma unroll
            for (int p = 0; p < 8; p++)
                fma2(acc[p], ws[j * 8 + p], xx[j]);
    }
    int r = slice * NCG + cg;
    float4* out = (float4*)(g_part + (((size_t)r * NK + k) * NB + b) * DO);
#pragma unroll
    for (int q = 0; q < 4; q++) {
        float2 lo = unpack2(acc[2*q]), hi = unpack2(acc[2*q + 1]);
        out[q] = make_float4(lo.x, lo.y, hi.x, hi.y);
    }
}

// out = squash(s2)
__global__ void k_squashF(float* __restrict__ out) {
    int t = blockIdx.x * blockDim.x + threadIdx.x;
    if (t >= NB * NK) return;
    float s[DO]; float sq = 0.f;
#pragma unroll
    for (int i = 0; i < DO; i++) { s[i] = g_s[t * DO + i]; sq += s[i] * s[i]; }
    float scale = (sq / (1.f + sq)) * rsqrtf(sq + EPSQ);
#pragma unroll
    for (int i = 0; i < DO; i++) out[t * DO + i] = s[i] * scale;
}

extern "C" void kernel_launch(void* const* d_in, const int* in_sizes, int n_in,
                              void* d_out, int out_size) {
    const float* x = (const float*)d_in[0];
    const float* W = (const float*)d_in[1];
    if (n_in >= 2 && in_sizes[0] == 8388608 && in_sizes[1] == 1048576) {
        const float* t = x; x = W; W = t;   // defensive order swap
    }
    float* out = (float*)d_out;

    dim3 passGrid(NSLICE, NK);
    dim3 passBlk(256);

    k_transpose<<<(CIN * NB * DI + 255) / 256, 256>>>(x);
    k_packW   <<<(NK * CIN * DI + 255) / 256, 256>>>(W);
    k_passA   <<<passGrid, passBlk>>>();
    k_reduce  <<<(NK * NB * 4 + 255) / 256, 256>>>();
    k_squash1 <<<(NB * NK + 127) / 128, 128>>>();
    k_passC   <<<passGrid, passBlk>>>();
    k_softmax <<<(CIN * NB + 255) / 256, 256>>>();
    k_passE   <<<passGrid, passBlk>>>();
    k_reduce  <<<(NK * NB * 4 + 255) / 256, 256>>>();
    k_squashF <<<(NB * NK + 127) / 128, 128>>>(out);
}

// round 5
// speedup vs baseline: 2.5754x; 1.3911x over previous
#include <cuda_runtime.h>
#include <math.h>

#define CIN 2048
#define NB  64
#define NK  32
#define DI  8
#define DO  16
#define EPSQ 1e-7f
#define CPB 64            // c per block
#define CSTRIDE 132       // padded smem stride per c (floats)

typedef unsigned long long ull;

// ---- scratch ----
__device__ float g_xT2[CIN * NB * DI];           // xT2[c][b][j] (4 MB)
__device__ float g_s  [NB * NK * DO];            // s accumulator
__device__ float g_v1 [NB * NK * DO];            // v after iter 1
__device__ float g_a  [(size_t)NK * CIN * NB];   // aT[k][c][b] -> cc (16 MB)

// ---- f32x2 helpers ----
__device__ __forceinline__ void fma2(ull& d, ull a, ull b) {
    asm("fma.rn.f32x2 %0, %1, %2, %0;" : "+l"(d) : "l"(a), "l"(b));
}
__device__ __forceinline__ ull pack2(float lo, float hi) {
    ull r; asm("mov.b64 %0, {%1, %2};" : "=l"(r) : "f"(lo), "f"(hi)); return r;
}
__device__ __forceinline__ float2 unpack2(ull v) {
    float2 f; asm("mov.b64 {%0, %1}, %2;" : "=f"(f.x), "=f"(f.y) : "l"(v)); return f;
}

__global__ void k_zero_s() {
    int t = blockIdx.x * blockDim.x + threadIdx.x;
    if (t < NB * NK * DO) g_s[t] = 0.f;
}

// xT2[(c*64+b)*8+j] = x[b][c][j]
__global__ void k_transpose(const float* __restrict__ x) {
    int idx = blockIdx.x * blockDim.x + threadIdx.x;
    if (idx < CIN * NB * DI) {
        int j = idx & 7, b = (idx >> 3) & 63, c = idx >> 9;
        g_xT2[idx] = __ldg(&x[(b * CIN + c) * DI + j]);
    }
}

// Load W tile [64c][16i][8j] -> sW[c][j][i] with padded stride
__device__ __forceinline__ void load_w_tile(float* sW, const float* __restrict__ W,
                                            int k, int c0) {
    const float4* src = (const float4*)(W + ((size_t)k * CIN + c0) * (DO * DI));
#pragma unroll
    for (int r = 0; r < 8; r++) {
        int idx = threadIdx.x + r * 256;            // 2048 float4
        float4 v = __ldg(&src[idx]);
        int cp = idx >> 5, i = (idx >> 1) & 15, jq = idx & 1;
        float* d = &sW[cp * CSTRIDE + i];
        d[(4 * jq + 0) * 16] = v.x;
        d[(4 * jq + 1) * 16] = v.y;
        d[(4 * jq + 2) * 16] = v.z;
        d[(4 * jq + 3) * 16] = v.w;
    }
}

// block reduce acc[4][8] over 16 c-groups, then atomicAdd into g_s
__device__ __forceinline__ void block_reduce_s(float* red, ull acc[4][8],
                                               int bq, int cg, int k) {
#pragma unroll
    for (int half = 0; half < 2; half++) {
        __syncthreads();
#pragma unroll
        for (int bb = 0; bb < 2; bb++) {
            int bi = 2 * half + bb;
            float* row = &red[(((size_t)cg * 16 + bq) * 2 + bb) * 17];
#pragma unroll
            for (int p = 0; p < 8; p++) {
                float2 f = unpack2(acc[bi][p]);
                row[2 * p]     = f.x;
                row[2 * p + 1] = f.y;
            }
        }
        __syncthreads();
#pragma unroll
        for (int w = 0; w < 2; w++) {
            int u = threadIdx.x + w * 256;          // 512 outputs (bq2,bb2,i)
            int i = u & 15, bb2 = (u >> 4) & 1, bq2 = u >> 5;
            float s = 0.f;
#pragma unroll
            for (int cgi = 0; cgi < 16; cgi++)
                s += red[((cgi * 16 + bq2) * 2 + bb2) * 17 + i];
            int b = bq2 + 16 * (2 * half + bb2);
            atomicAdd(&g_s[(b * NK + k) * DO + i], s);
        }
    }
}

// ---------- Pass A ----------
__global__ void __launch_bounds__(256) k_passA(const float* __restrict__ W) {
    __shared__ float sW[512 * 17];                  // 34816 B; >= 64*132
    int k = blockIdx.y, c0 = blockIdx.x * CPB;
    load_w_tile(sW, W, k, c0);
    __syncthreads();

    int bq = threadIdx.x & 15, cg = threadIdx.x >> 4;
    ull acc[4][8];
#pragma unroll
    for (int bi = 0; bi < 4; bi++)
#pragma unroll
        for (int p = 0; p < 8; p++) acc[bi][p] = 0ull;

#pragma unroll
    for (int it = 0; it < 4; it++) {
        int cl = cg + 16 * it;
        int c  = c0 + cl;
        const ull* ws = (const ull*)&sW[cl * CSTRIDE];
        float xr[4][8];
#pragma unroll
        for (int bi = 0; bi < 4; bi++) {
            const float4* xp = (const float4*)&g_xT2[((size_t)c * NB + (bq + 16 * bi)) * DI];
            float4 a = xp[0], b4 = xp[1];
            xr[bi][0] = a.x;  xr[bi][1] = a.y;  xr[bi][2] = a.z;  xr[bi][3] = a.w;
            xr[bi][4] = b4.x; xr[bi][5] = b4.y; xr[bi][6] = b4.z; xr[bi][7] = b4.w;
        }
#pragma unroll
        for (int j = 0; j < 8; j++) {
            ull xx[4];
#pragma unroll
            for (int bi = 0; bi < 4; bi++) xx[bi] = pack2(xr[bi][j], xr[bi][j]);
#pragma unroll
            for (int p = 0; p < 8; p++) {
                ull w = ws[j * 8 + p];
#pragma unroll
                for (int bi = 0; bi < 4; bi++) fma2(acc[bi][p], w, xx[bi]);
            }
        }
    }
    block_reduce_s(sW, acc, bq, cg, k);
}

// v1 = squash(s/32)
__global__ void k_squash1() {
    int t = blockIdx.x * blockDim.x + threadIdx.x;
    if (t >= NB * NK) return;
    float s[DO]; float sq = 0.f;
#pragma unroll
    for (int i = 0; i < DO; i++) { s[i] = g_s[t * DO + i] * (1.f / 32.f); sq += s[i] * s[i]; }
    float scale = (sq / (1.f + sq)) * rsqrtf(sq + EPSQ);
#pragma unroll
    for (int i = 0; i < DO; i++) g_v1[t * DO + i] = s[i] * scale;
}

// ---------- Pass C: aT[k][c][b] = sum_i u * v1 ----------
__global__ void __launch_bounds__(256) k_passC(const float* __restrict__ W) {
    __shared__ float sW[512 * 17];
    int k = blockIdx.y, c0 = blockIdx.x * CPB;
    load_w_tile(sW, W, k, c0);
    __syncthreads();

    int b0 = threadIdx.x & 31, cg = threadIdx.x >> 5;   // 8 c-groups, b-tile 2
    ull v2[2][8];
#pragma unroll
    for (int bi = 0; bi < 2; bi++) {
        const ull* vp = (const ull*)&g_v1[((b0 + 32 * bi) * NK + k) * DO];
#pragma unroll
        for (int p = 0; p < 8; p++) v2[bi][p] = vp[p];
    }

#pragma unroll
    for (int it = 0; it < 8; it++) {
        int cl = cg + 8 * it;
        int c  = c0 + cl;
        const ull* ws = (const ull*)&sW[cl * CSTRIDE];
        float xr[2][8];
#pragma unroll
        for (int bi = 0; bi < 2; bi++) {
            const float4* xp = (const float4*)&g_xT2[((size_t)c * NB + (b0 + 32 * bi)) * DI];
            float4 a = xp[0], b4 = xp[1];
            xr[bi][0] = a.x;  xr[bi][1] = a.y;  xr[bi][2] = a.z;  xr[bi][3] = a.w;
            xr[bi][4] = b4.x; xr[bi][5] = b4.y; xr[bi][6] = b4.z; xr[bi][7] = b4.w;
        }
        ull u2[2][8];
#pragma unroll
        for (int bi = 0; bi < 2; bi++)
#pragma unroll
            for (int p = 0; p < 8; p++) u2[bi][p] = 0ull;
#pragma unroll
        for (int j = 0; j < 8; j++) {
            ull xx0 = pack2(xr[0][j], xr[0][j]);
            ull xx1 = pack2(xr[1][j], xr[1][j]);
#pragma unroll
            for (int p = 0; p < 8; p++) {
                ull w = ws[j * 8 + p];
                fma2(u2[0][p], w, xx0);
                fma2(u2[1][p], w, xx1);
            }
        }
#pragma unroll
        for (int bi = 0; bi < 2; bi++) {
            ull a2 = 0ull;
#pragma unroll
            for (int p = 0; p < 8; p++) fma2(a2, u2[bi][p], v2[bi][p]);
            float2 af = unpack2(a2);
            g_a[((size_t)k * CIN + c) * NB + (b0 + 32 * bi)] = af.x + af.y;
        }
    }
}

// softmax over k, in place
__global__ void k_softmax() {
    int idx = blockIdx.x * blockDim.x + threadIdx.x;
    if (idx >= CIN * NB) return;
    float vals[NK]; float mx = -1e30f;
#pragma unroll
    for (int k = 0; k < NK; k++) {
        vals[k] = g_a[(size_t)k * (CIN * NB) + idx];
        mx = fmaxf(mx, vals[k]);
    }
    float sum = 0.f;
#pragma unroll
    for (int k = 0; k < NK; k++) { vals[k] = __expf(vals[k] - mx); sum += vals[k]; }
    float inv = 1.f / sum;
#pragma unroll
    for (int k = 0; k < NK; k++) g_a[(size_t)k * (CIN * NB) + idx] = vals[k] * inv;
}

// ---------- Pass E ----------
__global__ void __launch_bounds__(256) k_passE(const float* __restrict__ W) {
    __shared__ float sW[512 * 17];
    int k = blockIdx.y, c0 = blockIdx.x * CPB;
    load_w_tile(sW, W, k, c0);
    __syncthreads();

    int bq = threadIdx.x & 15, cg = threadIdx.x >> 4;
    ull acc[4][8];
#pragma unroll
    for (int bi = 0; bi < 4; bi++)
#pragma unroll
        for (int p = 0; p < 8; p++) acc[bi][p] = 0ull;

#pragma unroll
    for (int it = 0; it < 4; it++) {
        int cl = cg + 16 * it;
        int c  = c0 + cl;
        const ull* ws = (const ull*)&sW[cl * CSTRIDE];
        float xr[4][8];
#pragma unroll
        for (int bi = 0; bi < 4; bi++) {
            int b = bq + 16 * bi;
            float cc = g_a[((size_t)k * CIN + c) * NB + b];
            const float4* xp = (const float4*)&g_xT2[((size_t)c * NB + b) * DI];
            float4 a = xp[0], b4 = xp[1];
            xr[bi][0] = a.x * cc;  xr[bi][1] = a.y * cc;  xr[bi][2] = a.z * cc;  xr[bi][3] = a.w * cc;
            xr[bi][4] = b4.x * cc; xr[bi][5] = b4.y * cc; xr[bi][6] = b4.z * cc; xr[bi][7] = b4.w * cc;
        }
#pragma unroll
        for (int j = 0; j < 8; j++) {
            ull xx[4];
#pragma unroll
            for (int bi = 0; bi < 4; bi++) xx[bi] = pack2(xr[bi][j], xr[bi][j]);
#pragma unroll
            for (int p = 0; p < 8; p++) {
                ull w = ws[j * 8 + p];
#pragma unroll
                for (int bi = 0; bi < 4; bi++) fma2(acc[bi][p], w, xx[bi]);
            }
        }
    }
    block_reduce_s(sW, acc, bq, cg, k);
}

// out = squash(s2)
__global__ void k_squashF(float* __restrict__ out) {
    int t = blockIdx.x * blockDim.x + threadIdx.x;
    if (t >= NB * NK) return;
    float s[DO]; float sq = 0.f;
#pragma unroll
    for (int i = 0; i < DO; i++) { s[i] = g_s[t * DO + i]; sq += s[i] * s[i]; }
    float scale = (sq / (1.f + sq)) * rsqrtf(sq + EPSQ);
#pragma unroll
    for (int i = 0; i < DO; i++) out[t * DO + i] = s[i] * scale;
}

extern "C" void kernel_launch(void* const* d_in, const int* in_sizes, int n_in,
                              void* d_out, int out_size) {
    const float* x = (const float*)d_in[0];
    const float* W = (const float*)d_in[1];
    if (n_in >= 2 && in_sizes[0] == 8388608 && in_sizes[1] == 1048576) {
        const float* t = x; x = W; W = t;   // defensive order swap
    }
    float* out = (float*)d_out;

    dim3 passGrid(CIN / CPB, NK);   // (32, 32)
    dim3 passBlk(256);

    k_transpose<<<(CIN * NB * DI + 255) / 256, 256>>>(x);
    k_zero_s <<<(NB * NK * DO + 255) / 256, 256>>>();
    k_passA  <<<passGrid, passBlk>>>(W);
    k_squash1<<<(NB * NK + 127) / 128, 128>>>();
    k_passC  <<<passGrid, passBlk>>>(W);
    k_softmax<<<(CIN * NB + 255) / 256, 256>>>();
    k_zero_s <<<(NB * NK * DO + 255) / 256, 256>>>();
    k_passE  <<<passGrid, passBlk>>>(W);
    k_squashF<<<(NB * NK + 127) / 128, 128>>>(out);
}